// round 16
// baseline (speedup 1.0000x reference)
#include <cuda_runtime.h>
#include <cuda_bf16.h>
#include <cuda_fp8.h>
#include <cstdint>

#define NSMP  8192
#define NAX   512
#define DOUTC 256
#define NCOLS 8712
#define AOFF  512
#define OUTS  8448

/* ---- k_support tiling: BM=64, BN=128 ---- */
#define BM      64
#define BN      128
#define STAGES  3
#define ASTB    144                   /* smem row stride in BYTES (128 + 16 pad) */
#define A_STGB  (BM*ASTB)             /* 9216 B */
#define B_STGB  (BN*ASTB)             /* 18432 B */
#define STG_B   (A_STGB + B_STGB)     /* 27648 B */
#define SMEM_PIPE (STAGES*STG_B)      /* 82944 B -> 2 CTAs/SM */

/* ---- k_main v2 tiling: CTA 128x128, warp 64x64, 128 threads, 1 CTA/SM ---- */
#define BM2     128
#define BN2     128
#define A_STGB2 (BM2*ASTB)            /* 18432 B */
#define STG_B2  ((BM2+BN2)*ASTB)      /* 36864 B */
#define SMEM_MAIN2 (STAGES*STG_B2)    /* 110592 B */

#define SMEM_B8 (64*260*4)            /* 66560 B */

/* ---------------- scratch globals ---------------- */
__device__ float          g_part[256 * NSMP];           /* colsum partials of (A-1/2) */
__device__ float          g_dis[NSMP];
__device__ float          g_Spf[NSMP * DOUTC];          /* S' fp32, [j][c] */
__device__ float          g_bpart[32 * DOUTC];          /* partial colsums of S' (fp32) */
__device__ float          g_hb[DOUTC];                  /* 0.5 * colsum(S') exact */
__device__ __nv_bfloat16  g_WT[DOUTC * NAX];            /* W^T bf16 [c][k] */
__device__ __nv_bfloat16  g_Xb[(size_t)NSMP * NAX];     /* X bf16 [m][k] */
__device__ __align__(16) unsigned char g_A8[(size_t)NSMP * NSMP];  /* fp8(A - 1/2) */
__device__ __align__(16) unsigned char g_B8[(size_t)DOUTC * NSMP]; /* fp8(S')^T [c][j] */

/* ---------------- helpers ---------------- */
__device__ __forceinline__ uint32_t pk_bf2(float a, float b) {
    __nv_bfloat162 h = __floats2bfloat162_rn(a, b);
    return *reinterpret_cast<uint32_t*>(&h);
}
__device__ __forceinline__ uint32_t pk_e4m3_4(float a, float b, float c, float d) {
    uint32_t lo = (uint32_t)__nv_cvt_float2_to_fp8x2(make_float2(a, b), __NV_SATFINITE, __NV_E4M3);
    uint32_t hi = (uint32_t)__nv_cvt_float2_to_fp8x2(make_float2(c, d), __NV_SATFINITE, __NV_E4M3);
    return lo | (hi << 16);
}
/* packed fp32x2 add (Blackwell) */
__device__ __forceinline__ uint64_t padd(uint64_t a, uint64_t b) {
    uint64_t r;
    asm("add.rn.f32x2 %0, %1, %2;" : "=l"(r) : "l"(a), "l"(b));
    return r;
}
/* two packed f32 pairs -> 4 e4m3 bytes (memory order x,y,z,w) */
__device__ __forceinline__ uint32_t cvt4(uint64_t pxy, uint64_t pzw) {
    uint32_t r;
    asm("{.reg .b32 l0,h0,l1,h1; .reg .b16 a,b;\n"
        " mov.b64 {l0,h0}, %1;\n"
        " mov.b64 {l1,h1}, %2;\n"
        " cvt.rn.satfinite.e4m3x2.f32 a, h0, l0;\n"
        " cvt.rn.satfinite.e4m3x2.f32 b, h1, l1;\n"
        " mov.b32 %0, {a,b};}"
        : "=r"(r) : "l"(pxy), "l"(pzw));
    return r;
}
__device__ __forceinline__ void mma16816(float* c,
    uint32_t a0, uint32_t a1, uint32_t a2, uint32_t a3, uint32_t b0, uint32_t b1) {
    asm volatile(
        "mma.sync.aligned.m16n8k16.row.col.f32.bf16.bf16.f32 "
        "{%0,%1,%2,%3},{%4,%5,%6,%7},{%8,%9},{%0,%1,%2,%3};\n"
        : "+f"(c[0]), "+f"(c[1]), "+f"(c[2]), "+f"(c[3])
        : "r"(a0), "r"(a1), "r"(a2), "r"(a3), "r"(b0), "r"(b1));
}
__device__ __forceinline__ void mma16832e(float* c,
    uint32_t a0, uint32_t a1, uint32_t a2, uint32_t a3, uint32_t b0, uint32_t b1) {
    asm volatile(
        "mma.sync.aligned.m16n8k32.row.col.f32.e4m3.e4m3.f32 "
        "{%0,%1,%2,%3},{%4,%5,%6,%7},{%8,%9},{%0,%1,%2,%3};\n"
        : "+f"(c[0]), "+f"(c[1]), "+f"(c[2]), "+f"(c[3])
        : "r"(a0), "r"(a1), "r"(a2), "r"(a3), "r"(b0), "r"(b1));
}
__device__ __forceinline__ void ldsm4(uint32_t& r0, uint32_t& r1, uint32_t& r2, uint32_t& r3,
                                      uint32_t saddr) {
    asm volatile("ldmatrix.sync.aligned.m8n8.x4.shared.b16 {%0,%1,%2,%3},[%4];\n"
                 : "=r"(r0), "=r"(r1), "=r"(r2), "=r"(r3) : "r"(saddr));
}
__device__ __forceinline__ void cpa16(uint32_t saddr, const void* g) {
    asm volatile("cp.async.cg.shared.global [%0],[%1],16;\n" :: "r"(saddr), "l"(g));
}

/* ------- kernel M: fused weight-transpose + X bf16 convert ------- */
__global__ void k_misc(const float* __restrict__ in, const float* __restrict__ w) {
    int b = blockIdx.x;
    if (b < 512) {                                   /* W^T: 512*256 = 131072 elems */
        int i = b * 256 + threadIdx.x;
        int k = i / DOUTC, c = i % DOUTC;
        g_WT[c * NAX + k] = __float2bfloat16(w[i]);
    } else {                                         /* Xb: 2048 blocks */
        int idx = (b - 512) * 256 + threadIdx.x;
        int row = idx >> 6, c8 = (idx & 63) * 8;
        const float* p = in + (size_t)row * NCOLS + c8;
        float4 a = *(const float4*)p, bb = *(const float4*)(p + 4);
        uint4 wv;
        wv.x = pk_bf2(a.x, a.y);  wv.y = pk_bf2(a.z, a.w);
        wv.z = pk_bf2(bb.x, bb.y); wv.w = pk_bf2(bb.z, bb.w);
        *(uint4*)(g_Xb + (size_t)row * NAX + c8) = wv;
    }
}

/* ------- kernel P: FUSED copy + colsum(A-1/2) + fp8(A-1/2), coalesced, high-occ ------- */
__global__ void k_prep_c(const float* __restrict__ in, float* __restrict__ out) {
    int j4 = (blockIdx.x * 256 + threadIdx.x) * 4;    /* grid.x = 8 -> 8192 cols */
    int r0 = blockIdx.y * 32;                         /* grid.y = 256 -> 8192 rows */
    const float* p = in + (size_t)r0 * NCOLS + AOFF + j4;
    float* po = out + (size_t)r0 * OUTS + 256 + j4;
    unsigned char* pa = g_A8 + (size_t)r0 * NSMP + j4;

    const uint64_t NH = 0xBF000000BF000000ull;        /* packed (-0.5f, -0.5f) */
    uint64_t s0 = 0ull, s1 = 0ull;

#pragma unroll 4
    for (int r = 0; r < 32; r++) {
        float4 v = *(const float4*)p;
        *(float4*)po = v;                             /* coalesced copy */
        uint64_t alo = padd(*reinterpret_cast<uint64_t*>(&v.x), NH);
        uint64_t ahi = padd(*reinterpret_cast<uint64_t*>(&v.z), NH);
        s0 = padd(s0, alo);
        s1 = padd(s1, ahi);
        *(uint32_t*)pa = cvt4(alo, ahi);              /* coalesced fp8 store */
        p += NCOLS; po += OUTS; pa += NSMP;
    }
    float2 lo = *reinterpret_cast<float2*>(&s0);
    float2 hi = *reinterpret_cast<float2*>(&s1);
    *(float4*)(g_part + (size_t)blockIdx.y * NSMP + j4) = make_float4(lo.x, lo.y, hi.x, hi.y);

    /* diagonal +1 fixup on the copy */
#pragma unroll
    for (int k = 0; k < 4; k++) {
        int j = j4 + k;
        if (j >= r0 && j < r0 + 32)
            out[(size_t)j * OUTS + 256 + j] += 1.0f;
    }
}

/* ---------------- kernel 1b: d^-1/2 (d = 1 + 4096 + sum of centered partials) ------- */
__global__ void k_dis() {
    int j = blockIdx.x * 256 + threadIdx.x;
    float s = 4097.0f;   /* identity (1) + re-centering (8192 * 0.5) */
    for (int b = 0; b < 256; b++) s += g_part[(size_t)b * NSMP + j];
    g_dis[j] = rsqrtf(s);
}

/* ------- kernel 2: S' = dis ⊙ (X @ W), bf16 cp.async+ldmatrix pipeline ------- */
__global__ void __launch_bounds__(256, 2) k_support() {
    extern __shared__ unsigned char shp[];
    const int t    = threadIdx.x;
    const int row0 = blockIdx.x * BM;
    const int col0 = blockIdx.y * BN;
    const int warp = t >> 5, lane = t & 31;
    const int wm = warp & 3, wn = warp >> 2;
    const int g  = lane >> 2, tq = lane & 3;

    uint32_t shb = (uint32_t)__cvta_generic_to_shared(shp);

    float acc[8][4];
#pragma unroll
    for (int f = 0; f < 8; f++) { acc[f][0]=acc[f][1]=acc[f][2]=acc[f][3]=0.f; }

    const __nv_bfloat16* ga = g_Xb + (size_t)(row0 + (t >> 2)) * NAX + (t & 3) * 16;
    const __nv_bfloat16* gb = g_WT + (size_t)(col0 + (t >> 1)) * NAX + (t & 1) * 32;
    const uint32_t sa_off = (uint32_t)((t >> 2) * ASTB + (t & 3) * 32);
    const uint32_t sb_off = (uint32_t)(A_STGB + (t >> 1) * ASTB + (t & 1) * 64);

    const uint32_t a_l = (uint32_t)((wm * 16 + (lane & 7) + ((lane >> 3) & 1) * 8) * ASTB
                                    + (lane >> 4) * 16);
    const uint32_t b_l = (uint32_t)(A_STGB +
                                    (wn * 64 + (lane & 7) + (lane >> 4) * 8) * ASTB
                                    + ((lane >> 3) & 1) * 16);

    auto PREF = [&](int stg, int k0) {
        uint32_t sb = shb + (uint32_t)(stg * STG_B);
        cpa16(sb + sa_off,      ga + k0);
        cpa16(sb + sa_off + 16, ga + k0 + 8);
        uint32_t sbB = sb + sb_off;
        const __nv_bfloat16* gB = gb + k0;
#pragma unroll
        for (int i = 0; i < 4; i++) cpa16(sbB + i * 16, gB + i * 8);
    };

    PREF(0, 0);
    asm volatile("cp.async.commit_group;\n" ::);
    PREF(1, 64);
    asm volatile("cp.async.commit_group;\n" ::);

    const int NKT = NAX / 64;   /* 8 */
    for (int kt = 0; kt < NKT; ++kt) {
        asm volatile("cp.async.wait_group 1;\n" ::);
        __syncthreads();

        if (kt + 2 < NKT) PREF((kt + 2) % STAGES, (kt + 2) * 64);
        asm volatile("cp.async.commit_group;\n" ::);

        uint32_t base = shb + (uint32_t)((kt % STAGES) * STG_B);
#pragma unroll
        for (int ks = 0; ks < 4; ks++) {
            uint32_t a0, a1, a2, a3;
            ldsm4(a0, a1, a2, a3, base + a_l + ks * 32);
#pragma unroll
            for (int nb = 0; nb < 4; nb++) {
                uint32_t b0, b1, b2, b3;
                ldsm4(b0, b1, b2, b3,
                      base + b_l + (uint32_t)(nb * (16 * ASTB)) + ks * 32);
                mma16816(acc[2 * nb],     a0, a1, a2, a3, b0, b1);
                mma16816(acc[2 * nb + 1], a0, a1, a2, a3, b2, b3);
            }
        }
    }

    int r1 = row0 + wm * 16 + g;
    int r2 = r1 + 8;
    float d1 = g_dis[r1], d2 = g_dis[r2];
#pragma unroll
    for (int f = 0; f < 8; f++) {
        int c = col0 + wn * 64 + (f >> 1) * 16 + (f & 1) * 8 + 2 * tq;
        *(float2*)(g_Spf + (size_t)r1 * DOUTC + c) =
            make_float2(acc[f][0] * d1, acc[f][1] * d1);
        *(float2*)(g_Spf + (size_t)r2 * DOUTC + c) =
            make_float2(acc[f][2] * d2, acc[f][3] * d2);
    }
}

/* ------- kernel BM: partial column sums of S' (fp32, exact) ------- */
__global__ void k_bmean() {
    int t = threadIdx.x, b = blockIdx.x;     /* grid 32 */
    const float* p = g_Spf + (size_t)b * 256 * DOUTC + t;
    float s = 0.f;
#pragma unroll 8
    for (int r = 0; r < 256; r++) s += p[(size_t)r * DOUTC];
    g_bpart[b * DOUTC + t] = s;
}

/* ---------------- kernel HB: g_hb[c] = 0.5 * colsum(S')  (EXACT fp32 sum) -------- */
__global__ void k_hb() {
    int c = threadIdx.x;
    float s = 0.f;
#pragma unroll
    for (int b = 0; b < 32; b++) s += g_bpart[b * DOUTC + c];
    g_hb[c] = 0.5f * s;
}

/* ------- kernel B8: transpose S' -> fp8 [c][j] (pure quantize, no sums) ------- */
__global__ void k_b8() {
    extern __shared__ float sm[];            /* [64][260] */
    int t = threadIdx.x, b = blockIdx.x;     /* grid 128 */
    int j0 = b * 64;
    for (int r = 0; r < 64; r++)
        sm[r * 260 + t] = g_Spf[(size_t)(j0 + r) * DOUTC + t];
    __syncthreads();

    int q = t & 3;
#pragma unroll
    for (int it = 0; it < 4; it++) {
        int c = (t >> 2) + it * 64;
        uint4 wv;
        uint32_t* wp = &wv.x;
#pragma unroll
        for (int wd = 0; wd < 4; wd++) {
            int jj = q * 16 + wd * 4;
            wp[wd] = pk_e4m3_4(sm[(jj + 0) * 260 + c], sm[(jj + 1) * 260 + c],
                               sm[(jj + 2) * 260 + c], sm[(jj + 3) * 260 + c]);
        }
        *(uint4*)(g_B8 + (size_t)c * NSMP + j0 + q * 16) = wv;
    }
}

/* ------- kernel 3 v2: fp8 GEMM, CTA 128x128, warp 64x64 (smem-traffic optimal) ------- */
__global__ void __launch_bounds__(128, 1) k_main(float* __restrict__ out) {
    extern __shared__ unsigned char sh8[];
    const int t    = threadIdx.x;
    const int row0 = blockIdx.x * BM2;
    const int col0 = blockIdx.y * BN2;
    const int warp = t >> 5, lane = t & 31;
    const int wm = warp & 1, wn = warp >> 1;          /* 2x2 warp grid */
    const int g  = lane >> 2, tq = lane & 3;

    uint32_t shb = (uint32_t)__cvta_generic_to_shared(sh8);

    float acc[4][4][2][4];                             /* [mb][nb][h][frag] */
#pragma unroll
    for (int mb = 0; mb < 4; mb++)
#pragma unroll
        for (int nb = 0; nb < 4; nb++)
#pragma unroll
            for (int h = 0; h < 2; h++) {
                acc[mb][nb][h][0]=acc[mb][nb][h][1]=acc[mb][nb][h][2]=acc[mb][nb][h][3]=0.f;
            }

    /* producer: 1 thread = 1 row (A and B), 8x16B each */
    const unsigned char* ga = g_A8 + (size_t)(row0 + t) * NSMP;
    const unsigned char* gb = g_B8 + (size_t)(col0 + t) * NSMP;
    const uint32_t sa_off = (uint32_t)(t * ASTB);
    const uint32_t sb_off = (uint32_t)(A_STGB2 + t * ASTB);

    /* consumer ldsm lane offsets (same lane formulas as proven 64x128 kernel) */
    const uint32_t a_l = (uint32_t)((wm * 64 + (lane & 7) + ((lane >> 3) & 1) * 8) * ASTB
                                    + (lane >> 4) * 16);
    const uint32_t b_l = (uint32_t)(A_STGB2 +
                                    (wn * 64 + (lane & 7) + (lane >> 4) * 8) * ASTB
                                    + ((lane >> 3) & 1) * 16);

    auto PREF = [&](int stg, int kbyte) {
        uint32_t sb = shb + (uint32_t)(stg * STG_B2);
        const unsigned char* gA = ga + kbyte;
        const unsigned char* gB = gb + kbyte;
#pragma unroll
        for (int i = 0; i < 8; i++) cpa16(sb + sa_off + i * 16, gA + i * 16);
#pragma unroll
        for (int i = 0; i < 8; i++) cpa16(sb + sb_off + i * 16, gB + i * 16);
    };

    PREF(0, 0);
    asm volatile("cp.async.commit_group;\n" ::);
    PREF(1, 128);
    asm volatile("cp.async.commit_group;\n" ::);

    const int NKT = NSMP / 128;   /* 64 */
    for (int kt = 0; kt < NKT; ++kt) {
        asm volatile("cp.async.wait_group 1;\n" ::);
        __syncthreads();

        if (kt + 2 < NKT) PREF((kt + 2) % STAGES, (kt + 2) * 128);
        asm volatile("cp.async.commit_group;\n" ::);

        uint32_t base = shb + (uint32_t)((kt % STAGES) * STG_B2);
#pragma unroll
        for (int ks = 0; ks < 4; ks++) {
            uint32_t af[4][4];
#pragma unroll
            for (int mb = 0; mb < 4; mb++)
                ldsm4(af[mb][0], af[mb][1], af[mb][2], af[mb][3],
                      base + a_l + (uint32_t)(mb * (16 * ASTB)) + ks * 32);
#pragma unroll
            for (int nb = 0; nb < 4; nb++) {
                uint32_t b0, b1, b2, b3;
                ldsm4(b0, b1, b2, b3,
                      base + b_l + (uint32_t)(nb * (16 * ASTB)) + ks * 32);
#pragma unroll
                for (int mb = 0; mb < 4; mb++) {
                    mma16832e(acc[mb][nb][0], af[mb][0], af[mb][1], af[mb][2], af[mb][3], b0, b1);
                    mma16832e(acc[mb][nb][1], af[mb][0], af[mb][1], af[mb][2], af[mb][3], b2, b3);
                }
            }
        }
    }

    /* epilogue: out[i,c] = dis[i]*(acc + hb[c] + S'[i,c]) */
#pragma unroll
    for (int mb = 0; mb < 4; mb++) {
        int r1 = row0 + wm * 64 + mb * 16 + g;
        int r2 = r1 + 8;
        float d1 = g_dis[r1], d2 = g_dis[r2];
#pragma unroll
        for (int nb = 0; nb < 4; nb++) {
#pragma unroll
            for (int h = 0; h < 2; h++) {
                int c = col0 + wn * 64 + nb * 16 + h * 8 + 2 * tq;
                float2 hb = *(const float2*)(g_hb + c);
                float2 s1 = *(const float2*)(g_Spf + (size_t)r1 * DOUTC + c);
                float2 s2 = *(const float2*)(g_Spf + (size_t)r2 * DOUTC + c);
                float* a4 = acc[mb][nb][h];
                *(float2*)(out + (size_t)r1 * OUTS + c) =
                    make_float2((a4[0] + hb.x + s1.x) * d1,
                                (a4[1] + hb.y + s1.y) * d1);
                *(float2*)(out + (size_t)r2 * OUTS + c) =
                    make_float2((a4[2] + hb.x + s2.x) * d2,
                                (a4[3] + hb.y + s2.y) * d2);
            }
        }
    }
}

/* ---------------- launch ---------------- */
extern "C" void kernel_launch(void* const* d_in, const int* in_sizes, int n_in,
                              void* d_out, int out_size) {
    const float* in = (const float*)d_in[0];
    const float* w  = (const float*)d_in[1];
    float* out = (float*)d_out;

    cudaFuncSetAttribute(k_support, cudaFuncAttributeMaxDynamicSharedMemorySize, SMEM_PIPE);
    cudaFuncSetAttribute(k_main,    cudaFuncAttributeMaxDynamicSharedMemorySize, SMEM_MAIN2);
    cudaFuncSetAttribute(k_b8,      cudaFuncAttributeMaxDynamicSharedMemorySize, SMEM_B8);

    k_misc<<<2560, 256>>>(in, w);                            /* #1: wt + xb fused */
    k_prep_c<<<dim3(8, 256), 256>>>(in, out);                /* #2 */
    k_dis<<<32, 256>>>();                                    /* #3 */
    k_support<<<dim3(NSMP / BM, DOUTC / BN), 256, SMEM_PIPE>>>();  /* #4 (profiled) */
    k_bmean<<<32, 256>>>();
    k_hb<<<1, 256>>>();
    k_b8<<<NSMP / 64, 256, SMEM_B8>>>();
    k_main<<<dim3(NSMP / BM2, DOUTC / BN2), 128, SMEM_MAIN2>>>(out);
}

// round 17
// speedup vs baseline: 1.1220x; 1.1220x over previous
#include <cuda_runtime.h>
#include <cuda_bf16.h>
#include <cuda_fp8.h>
#include <cstdint>

#define NSMP  8192
#define NAX   512
#define DOUTC 256
#define NCOLS 8712
#define AOFF  512
#define OUTS  8448

/* ---- k_support tiling: BM=64, BN=128 ---- */
#define BM      64
#define BN      128
#define STAGES  3
#define ASTB    144                   /* smem row stride in BYTES (128 + 16 pad) */
#define A_STGB  (BM*ASTB)             /* 9216 B */
#define B_STGB  (BN*ASTB)             /* 18432 B */
#define STG_B   (A_STGB + B_STGB)     /* 27648 B */
#define SMEM_PIPE (STAGES*STG_B)      /* 82944 B -> 2 CTAs/SM */

/* ---- k_main v3 tiling: CTA 128x128, warp 32x64, 256 threads, 1 CTA/SM ---- */
#define BM2     128
#define BN2     128
#define A_STGB2 (BM2*ASTB)            /* 18432 B */
#define STG_B2  ((BM2+BN2)*ASTB)      /* 36864 B */
#define SMEM_MAIN2 (STAGES*STG_B2)    /* 110592 B -> 1 CTA/SM */

#define SMEM_B8 (64*260*4)            /* 66560 B */

/* ---------------- scratch globals ---------------- */
__device__ float          g_part[256 * NSMP];           /* colsum partials of (A-1/2) */
__device__ float          g_dis[NSMP];
__device__ float          g_Spf[NSMP * DOUTC];          /* S' fp32, [j][c] */
__device__ float          g_bpart[32 * DOUTC];          /* partial colsums of S' (fp32) */
__device__ float          g_hb[DOUTC];                  /* 0.5 * colsum(S') exact */
__device__ __nv_bfloat16  g_WT[DOUTC * NAX];            /* W^T bf16 [c][k] */
__device__ __nv_bfloat16  g_Xb[(size_t)NSMP * NAX];     /* X bf16 [m][k] */
__device__ __align__(16) unsigned char g_A8[(size_t)NSMP * NSMP];  /* fp8(A - 1/2) */
__device__ __align__(16) unsigned char g_B8[(size_t)DOUTC * NSMP]; /* fp8(S')^T [c][j] */

/* ---------------- helpers ---------------- */
__device__ __forceinline__ uint32_t pk_bf2(float a, float b) {
    __nv_bfloat162 h = __floats2bfloat162_rn(a, b);
    return *reinterpret_cast<uint32_t*>(&h);
}
__device__ __forceinline__ uint32_t pk_e4m3_4(float a, float b, float c, float d) {
    uint32_t lo = (uint32_t)__nv_cvt_float2_to_fp8x2(make_float2(a, b), __NV_SATFINITE, __NV_E4M3);
    uint32_t hi = (uint32_t)__nv_cvt_float2_to_fp8x2(make_float2(c, d), __NV_SATFINITE, __NV_E4M3);
    return lo | (hi << 16);
}
/* packed fp32x2 add (Blackwell) */
__device__ __forceinline__ uint64_t padd(uint64_t a, uint64_t b) {
    uint64_t r;
    asm("add.rn.f32x2 %0, %1, %2;" : "=l"(r) : "l"(a), "l"(b));
    return r;
}
/* two packed f32 pairs -> 4 e4m3 bytes (memory order x,y,z,w) */
__device__ __forceinline__ uint32_t cvt4(uint64_t pxy, uint64_t pzw) {
    uint32_t r;
    asm("{.reg .b32 l0,h0,l1,h1; .reg .b16 a,b;\n"
        " mov.b64 {l0,h0}, %1;\n"
        " mov.b64 {l1,h1}, %2;\n"
        " cvt.rn.satfinite.e4m3x2.f32 a, h0, l0;\n"
        " cvt.rn.satfinite.e4m3x2.f32 b, h1, l1;\n"
        " mov.b32 %0, {a,b};}"
        : "=r"(r) : "l"(pxy), "l"(pzw));
    return r;
}
__device__ __forceinline__ void mma16816(float* c,
    uint32_t a0, uint32_t a1, uint32_t a2, uint32_t a3, uint32_t b0, uint32_t b1) {
    asm volatile(
        "mma.sync.aligned.m16n8k16.row.col.f32.bf16.bf16.f32 "
        "{%0,%1,%2,%3},{%4,%5,%6,%7},{%8,%9},{%0,%1,%2,%3};\n"
        : "+f"(c[0]), "+f"(c[1]), "+f"(c[2]), "+f"(c[3])
        : "r"(a0), "r"(a1), "r"(a2), "r"(a3), "r"(b0), "r"(b1));
}
__device__ __forceinline__ void mma16832e(float* c,
    uint32_t a0, uint32_t a1, uint32_t a2, uint32_t a3, uint32_t b0, uint32_t b1) {
    asm volatile(
        "mma.sync.aligned.m16n8k32.row.col.f32.e4m3.e4m3.f32 "
        "{%0,%1,%2,%3},{%4,%5,%6,%7},{%8,%9},{%0,%1,%2,%3};\n"
        : "+f"(c[0]), "+f"(c[1]), "+f"(c[2]), "+f"(c[3])
        : "r"(a0), "r"(a1), "r"(a2), "r"(a3), "r"(b0), "r"(b1));
}
__device__ __forceinline__ void ldsm4(uint32_t& r0, uint32_t& r1, uint32_t& r2, uint32_t& r3,
                                      uint32_t saddr) {
    asm volatile("ldmatrix.sync.aligned.m8n8.x4.shared.b16 {%0,%1,%2,%3},[%4];\n"
                 : "=r"(r0), "=r"(r1), "=r"(r2), "=r"(r3) : "r"(saddr));
}
__device__ __forceinline__ void cpa16(uint32_t saddr, const void* g) {
    asm volatile("cp.async.cg.shared.global [%0],[%1],16;\n" :: "r"(saddr), "l"(g));
}

/* ------- kernel M: fused weight-transpose + X bf16 convert ------- */
__global__ void k_misc(const float* __restrict__ in, const float* __restrict__ w) {
    int b = blockIdx.x;
    if (b < 512) {                                   /* W^T: 512*256 = 131072 elems */
        int i = b * 256 + threadIdx.x;
        int k = i / DOUTC, c = i % DOUTC;
        g_WT[c * NAX + k] = __float2bfloat16(w[i]);
    } else {                                         /* Xb: 2048 blocks */
        int idx = (b - 512) * 256 + threadIdx.x;
        int row = idx >> 6, c8 = (idx & 63) * 8;
        const float* p = in + (size_t)row * NCOLS + c8;
        float4 a = *(const float4*)p, bb = *(const float4*)(p + 4);
        uint4 wv;
        wv.x = pk_bf2(a.x, a.y);  wv.y = pk_bf2(a.z, a.w);
        wv.z = pk_bf2(bb.x, bb.y); wv.w = pk_bf2(bb.z, bb.w);
        *(uint4*)(g_Xb + (size_t)row * NAX + c8) = wv;
    }
}

/* ------- kernel P: FUSED copy + colsum(A-1/2) + fp8(A-1/2), coalesced, high-occ ------- */
__global__ void k_prep_c(const float* __restrict__ in, float* __restrict__ out) {
    int j4 = (blockIdx.x * 256 + threadIdx.x) * 4;    /* grid.x = 8 -> 8192 cols */
    int r0 = blockIdx.y * 32;                         /* grid.y = 256 -> 8192 rows */
    const float* p = in + (size_t)r0 * NCOLS + AOFF + j4;
    float* po = out + (size_t)r0 * OUTS + 256 + j4;
    unsigned char* pa = g_A8 + (size_t)r0 * NSMP + j4;

    const uint64_t NH = 0xBF000000BF000000ull;        /* packed (-0.5f, -0.5f) */
    uint64_t s0 = 0ull, s1 = 0ull;

#pragma unroll 4
    for (int r = 0; r < 32; r++) {
        float4 v = *(const float4*)p;
        *(float4*)po = v;                             /* coalesced copy */
        uint64_t alo = padd(*reinterpret_cast<uint64_t*>(&v.x), NH);
        uint64_t ahi = padd(*reinterpret_cast<uint64_t*>(&v.z), NH);
        s0 = padd(s0, alo);
        s1 = padd(s1, ahi);
        *(uint32_t*)pa = cvt4(alo, ahi);              /* coalesced fp8 store */
        p += NCOLS; po += OUTS; pa += NSMP;
    }
    float2 lo = *reinterpret_cast<float2*>(&s0);
    float2 hi = *reinterpret_cast<float2*>(&s1);
    *(float4*)(g_part + (size_t)blockIdx.y * NSMP + j4) = make_float4(lo.x, lo.y, hi.x, hi.y);

    /* diagonal +1 fixup on the copy */
#pragma unroll
    for (int k = 0; k < 4; k++) {
        int j = j4 + k;
        if (j >= r0 && j < r0 + 32)
            out[(size_t)j * OUTS + 256 + j] += 1.0f;
    }
}

/* ---------------- kernel 1b: d^-1/2 (d = 1 + 4096 + sum of centered partials) ------- */
__global__ void k_dis() {
    int j = blockIdx.x * 256 + threadIdx.x;
    float s = 4097.0f;   /* identity (1) + re-centering (8192 * 0.5) */
    for (int b = 0; b < 256; b++) s += g_part[(size_t)b * NSMP + j];
    g_dis[j] = rsqrtf(s);
}

/* ------- kernel 2: S' = dis ⊙ (X @ W), bf16 cp.async+ldmatrix pipeline ------- */
__global__ void __launch_bounds__(256, 2) k_support() {
    extern __shared__ unsigned char shp[];
    const int t    = threadIdx.x;
    const int row0 = blockIdx.x * BM;
    const int col0 = blockIdx.y * BN;
    const int warp = t >> 5, lane = t & 31;
    const int wm = warp & 3, wn = warp >> 2;
    const int g  = lane >> 2, tq = lane & 3;

    uint32_t shb = (uint32_t)__cvta_generic_to_shared(shp);

    float acc[8][4];
#pragma unroll
    for (int f = 0; f < 8; f++) { acc[f][0]=acc[f][1]=acc[f][2]=acc[f][3]=0.f; }

    const __nv_bfloat16* ga = g_Xb + (size_t)(row0 + (t >> 2)) * NAX + (t & 3) * 16;
    const __nv_bfloat16* gb = g_WT + (size_t)(col0 + (t >> 1)) * NAX + (t & 1) * 32;
    const uint32_t sa_off = (uint32_t)((t >> 2) * ASTB + (t & 3) * 32);
    const uint32_t sb_off = (uint32_t)(A_STGB + (t >> 1) * ASTB + (t & 1) * 64);

    const uint32_t a_l = (uint32_t)((wm * 16 + (lane & 7) + ((lane >> 3) & 1) * 8) * ASTB
                                    + (lane >> 4) * 16);
    const uint32_t b_l = (uint32_t)(A_STGB +
                                    (wn * 64 + (lane & 7) + (lane >> 4) * 8) * ASTB
                                    + ((lane >> 3) & 1) * 16);

    auto PREF = [&](int stg, int k0) {
        uint32_t sb = shb + (uint32_t)(stg * STG_B);
        cpa16(sb + sa_off,      ga + k0);
        cpa16(sb + sa_off + 16, ga + k0 + 8);
        uint32_t sbB = sb + sb_off;
        const __nv_bfloat16* gB = gb + k0;
#pragma unroll
        for (int i = 0; i < 4; i++) cpa16(sbB + i * 16, gB + i * 8);
    };

    PREF(0, 0);
    asm volatile("cp.async.commit_group;\n" ::);
    PREF(1, 64);
    asm volatile("cp.async.commit_group;\n" ::);

    const int NKT = NAX / 64;   /* 8 */
    for (int kt = 0; kt < NKT; ++kt) {
        asm volatile("cp.async.wait_group 1;\n" ::);
        __syncthreads();

        if (kt + 2 < NKT) PREF((kt + 2) % STAGES, (kt + 2) * 64);
        asm volatile("cp.async.commit_group;\n" ::);

        uint32_t base = shb + (uint32_t)((kt % STAGES) * STG_B);
#pragma unroll
        for (int ks = 0; ks < 4; ks++) {
            uint32_t a0, a1, a2, a3;
            ldsm4(a0, a1, a2, a3, base + a_l + ks * 32);
#pragma unroll
            for (int nb = 0; nb < 4; nb++) {
                uint32_t b0, b1, b2, b3;
                ldsm4(b0, b1, b2, b3,
                      base + b_l + (uint32_t)(nb * (16 * ASTB)) + ks * 32);
                mma16816(acc[2 * nb],     a0, a1, a2, a3, b0, b1);
                mma16816(acc[2 * nb + 1], a0, a1, a2, a3, b2, b3);
            }
        }
    }

    int r1 = row0 + wm * 16 + g;
    int r2 = r1 + 8;
    float d1 = g_dis[r1], d2 = g_dis[r2];
#pragma unroll
    for (int f = 0; f < 8; f++) {
        int c = col0 + wn * 64 + (f >> 1) * 16 + (f & 1) * 8 + 2 * tq;
        *(float2*)(g_Spf + (size_t)r1 * DOUTC + c) =
            make_float2(acc[f][0] * d1, acc[f][1] * d1);
        *(float2*)(g_Spf + (size_t)r2 * DOUTC + c) =
            make_float2(acc[f][2] * d2, acc[f][3] * d2);
    }
}

/* ------- kernel BM: partial column sums of S' (fp32, exact) ------- */
__global__ void k_bmean() {
    int t = threadIdx.x, b = blockIdx.x;     /* grid 32 */
    const float* p = g_Spf + (size_t)b * 256 * DOUTC + t;
    float s = 0.f;
#pragma unroll 8
    for (int r = 0; r < 256; r++) s += p[(size_t)r * DOUTC];
    g_bpart[b * DOUTC + t] = s;
}

/* ---------------- kernel HB: g_hb[c] = 0.5 * colsum(S')  (EXACT fp32 sum) -------- */
__global__ void k_hb() {
    int c = threadIdx.x;
    float s = 0.f;
#pragma unroll
    for (int b = 0; b < 32; b++) s += g_bpart[b * DOUTC + c];
    g_hb[c] = 0.5f * s;
}

/* ------- kernel B8: transpose S' -> fp8 [c][j] (pure quantize, no sums) ------- */
__global__ void k_b8() {
    extern __shared__ float sm[];            /* [64][260] */
    int t = threadIdx.x, b = blockIdx.x;     /* grid 128 */
    int j0 = b * 64;
    for (int r = 0; r < 64; r++)
        sm[r * 260 + t] = g_Spf[(size_t)(j0 + r) * DOUTC + t];
    __syncthreads();

    int q = t & 3;
#pragma unroll
    for (int it = 0; it < 4; it++) {
        int c = (t >> 2) + it * 64;
        uint4 wv;
        uint32_t* wp = &wv.x;
#pragma unroll
        for (int wd = 0; wd < 4; wd++) {
            int jj = q * 16 + wd * 4;
            wp[wd] = pk_e4m3_4(sm[(jj + 0) * 260 + c], sm[(jj + 1) * 260 + c],
                               sm[(jj + 2) * 260 + c], sm[(jj + 3) * 260 + c]);
        }
        *(uint4*)(g_B8 + (size_t)c * NSMP + j0 + q * 16) = wv;
    }
}

/* --- kernel 3 v3: fp8 GEMM, CTA 128x128, warp 32x64, 256 threads, 1 CTA/SM --- */
__global__ void __launch_bounds__(256, 1) k_main(float* __restrict__ out) {
    extern __shared__ unsigned char sh8[];
    const int t    = threadIdx.x;
    const int row0 = blockIdx.x * BM2;
    const int col0 = blockIdx.y * BN2;
    const int warp = t >> 5, lane = t & 31;
    const int wm = warp & 3, wn = warp >> 2;          /* 4x2 warp grid: m32 x n64 tiles */
    const int g  = lane >> 2, tq = lane & 3;

    uint32_t shb = (uint32_t)__cvta_generic_to_shared(sh8);

    float acc[2][4][2][4];                             /* [mb][nb][h][frag] */
#pragma unroll
    for (int mb = 0; mb < 2; mb++)
#pragma unroll
        for (int nb = 0; nb < 4; nb++)
#pragma unroll
            for (int h = 0; h < 2; h++) {
                acc[mb][nb][h][0]=acc[mb][nb][h][1]=acc[mb][nb][h][2]=acc[mb][nb][h][3]=0.f;
            }

    /* producer: thread t>>1 = row, (t&1)*64 byte offset; 4x16B per operand */
    const unsigned char* ga = g_A8 + (size_t)(row0 + (t >> 1)) * NSMP + (t & 1) * 64;
    const unsigned char* gb = g_B8 + (size_t)(col0 + (t >> 1)) * NSMP + (t & 1) * 64;
    const uint32_t sa_off = (uint32_t)((t >> 1) * ASTB + (t & 1) * 64);
    const uint32_t sb_off = (uint32_t)(A_STGB2 + (t >> 1) * ASTB + (t & 1) * 64);

    /* consumer ldsm lane offsets */
    const uint32_t a_l = (uint32_t)((wm * 32 + (lane & 7) + ((lane >> 3) & 1) * 8) * ASTB
                                    + (lane >> 4) * 16);
    const uint32_t b_l = (uint32_t)(A_STGB2 +
                                    (wn * 64 + (lane & 7) + (lane >> 4) * 8) * ASTB
                                    + ((lane >> 3) & 1) * 16);

    auto PREF = [&](int stg, int kbyte) {
        uint32_t sb = shb + (uint32_t)(stg * STG_B2);
        const unsigned char* gA = ga + kbyte;
        const unsigned char* gB = gb + kbyte;
#pragma unroll
        for (int i = 0; i < 4; i++) cpa16(sb + sa_off + i * 16, gA + i * 16);
#pragma unroll
        for (int i = 0; i < 4; i++) cpa16(sb + sb_off + i * 16, gB + i * 16);
    };

    PREF(0, 0);
    asm volatile("cp.async.commit_group;\n" ::);
    PREF(1, 128);
    asm volatile("cp.async.commit_group;\n" ::);

    const int NKT = NSMP / 128;   /* 64 */
    for (int kt = 0; kt < NKT; ++kt) {
        asm volatile("cp.async.wait_group 1;\n" ::);
        __syncthreads();

        if (kt + 2 < NKT) PREF((kt + 2) % STAGES, (kt + 2) * 128);
        asm volatile("cp.async.commit_group;\n" ::);

        uint32_t base = shb + (uint32_t)((kt % STAGES) * STG_B2);
#pragma unroll
        for (int ks = 0; ks < 4; ks++) {
            uint32_t af[2][4];
#pragma unroll
            for (int mb = 0; mb < 2; mb++)
                ldsm4(af[mb][0], af[mb][1], af[mb][2], af[mb][3],
                      base + a_l + (uint32_t)(mb * (16 * ASTB)) + ks * 32);
#pragma unroll
            for (int nb = 0; nb < 4; nb++) {
                uint32_t b0, b1, b2, b3;
                ldsm4(b0, b1, b2, b3,
                      base + b_l + (uint32_t)(nb * (16 * ASTB)) + ks * 32);
#pragma unroll
                for (int mb = 0; mb < 2; mb++) {
                    mma16832e(acc[mb][nb][0], af[mb][0], af[mb][1], af[mb][2], af[mb][3], b0, b1);
                    mma16832e(acc[mb][nb][1], af[mb][0], af[mb][1], af[mb][2], af[mb][3], b2, b3);
                }
            }
        }
    }

    /* epilogue: out[i,c] = dis[i]*(acc + hb[c] + S'[i,c])
       hb = 0.5*colsum(S') exactly cancels the A-centering + fp8-B bias */
#pragma unroll
    for (int mb = 0; mb < 2; mb++) {
        int r1 = row0 + wm * 32 + mb * 16 + g;
        int r2 = r1 + 8;
        float d1 = g_dis[r1], d2 = g_dis[r2];
#pragma unroll
        for (int nb = 0; nb < 4; nb++) {
#pragma unroll
            for (int h = 0; h < 2; h++) {
                int c = col0 + wn * 64 + nb * 16 + h * 8 + 2 * tq;
                float2 hb = *(const float2*)(g_hb + c);
                float2 s1 = *(const float2*)(g_Spf + (size_t)r1 * DOUTC + c);
                float2 s2 = *(const float2*)(g_Spf + (size_t)r2 * DOUTC + c);
                float* a4 = acc[mb][nb][h];
                *(float2*)(out + (size_t)r1 * OUTS + c) =
                    make_float2((a4[0] + hb.x + s1.x) * d1,
                                (a4[1] + hb.y + s1.y) * d1);
                *(float2*)(out + (size_t)r2 * OUTS + c) =
                    make_float2((a4[2] + hb.x + s2.x) * d2,
                                (a4[3] + hb.y + s2.y) * d2);
            }
        }
    }
}

/* ---------------- launch ---------------- */
extern "C" void kernel_launch(void* const* d_in, const int* in_sizes, int n_in,
                              void* d_out, int out_size) {
    const float* in = (const float*)d_in[0];
    const float* w  = (const float*)d_in[1];
    float* out = (float*)d_out;

    cudaFuncSetAttribute(k_support, cudaFuncAttributeMaxDynamicSharedMemorySize, SMEM_PIPE);
    cudaFuncSetAttribute(k_main,    cudaFuncAttributeMaxDynamicSharedMemorySize, SMEM_MAIN2);
    cudaFuncSetAttribute(k_b8,      cudaFuncAttributeMaxDynamicSharedMemorySize, SMEM_B8);

    k_misc<<<2560, 256>>>(in, w);                            /* #1: wt + xb fused */
    k_prep_c<<<dim3(8, 256), 256>>>(in, out);                /* #2 */
    k_dis<<<32, 256>>>();                                    /* #3 */
    k_support<<<dim3(NSMP / BM, DOUTC / BN), 256, SMEM_PIPE>>>();  /* #4 (profiled) */
    k_bmean<<<32, 256>>>();
    k_hb<<<1, 256>>>();
    k_b8<<<NSMP / 64, 256, SMEM_B8>>>();
    k_main<<<dim3(NSMP / BM2, DOUTC / BN2), 256, SMEM_MAIN2>>>(out);
}